// round 8
// baseline (speedup 1.0000x reference)
#include <cuda_runtime.h>
#include <cuda_bf16.h>
#include <math.h>
#include <stdint.h>

#define BATCH 4
#define SEQ   2048
#define DIM   1024
#define MQ    (BATCH * SEQ)      // 8192

// ---------------------------------------------------------------------------
// Device scratch (no allocation allowed)
// ---------------------------------------------------------------------------
__device__ float          g_S[BATCH * SEQ * SEQ];            // fp32 scores
__device__ __nv_bfloat16  g_Xhi[MQ * DIM],  g_Xlo[MQ * DIM];
__device__ __nv_bfloat16  g_Wqhi[DIM * DIM], g_Wqlo[DIM * DIM];
__device__ __nv_bfloat16  g_Wkhi[DIM * DIM], g_Wklo[DIM * DIM];
__device__ __nv_bfloat16  g_Wvhi[DIM * DIM], g_Wvlo[DIM * DIM];
__device__ __nv_bfloat16  g_Qhi[MQ * DIM],  g_Qlo[MQ * DIM];
__device__ __nv_bfloat16  g_Khi[MQ * DIM],  g_Klo[MQ * DIM];
__device__ __nv_bfloat16  g_Vthi[MQ * DIM], g_Vtlo[MQ * DIM];   // [B][D][S]
__device__ __nv_bfloat16  g_Phi[BATCH * SEQ * SEQ], g_Plo[BATCH * SEQ * SEQ];

// ---------------------------------------------------------------------------
// PTX helpers (sm_80-class ISA: cp.async, ldmatrix, mma.sync)
// ---------------------------------------------------------------------------
__device__ __forceinline__ uint32_t smem_u32(const void* p) {
    uint32_t a;
    asm("{ .reg .u64 t; cvta.to.shared.u64 t, %1; cvt.u32.u64 %0, t; }"
        : "=r"(a) : "l"(p));
    return a;
}

#define CP_ASYNC16(dst, src) \
    asm volatile("cp.async.cg.shared.global [%0], [%1], 16;" :: "r"(dst), "l"(src))
#define CP_COMMIT() asm volatile("cp.async.commit_group;" ::: "memory")
#define CP_WAIT1()  asm volatile("cp.async.wait_group 1;"  ::: "memory")
#define CP_WAIT0()  asm volatile("cp.async.wait_group 0;"  ::: "memory")

#define LDSM_X4(r0, r1, r2, r3, addr) \
    asm volatile("ldmatrix.sync.aligned.m8n8.x4.shared.b16 {%0,%1,%2,%3}, [%4];" \
                 : "=r"(r0), "=r"(r1), "=r"(r2), "=r"(r3) : "r"(addr))
#define LDSM_X2(r0, r1, addr) \
    asm volatile("ldmatrix.sync.aligned.m8n8.x2.shared.b16 {%0,%1}, [%2];" \
                 : "=r"(r0), "=r"(r1) : "r"(addr))

#define MMA16816(d, a, b) \
    asm volatile("mma.sync.aligned.m16n8k16.row.col.f32.bf16.bf16.f32 " \
                 "{%0,%1,%2,%3},{%4,%5,%6,%7},{%8,%9},{%0,%1,%2,%3};" \
                 : "+f"((d)[0]), "+f"((d)[1]), "+f"((d)[2]), "+f"((d)[3]) \
                 : "r"((a)[0]), "r"((a)[1]), "r"((a)[2]), "r"((a)[3]), \
                   "r"((b)[0]), "r"((b)[1]))

#define SWZ(bo) ((bo) ^ (((bo) >> 3) & 0x70))

// ---------------------------------------------------------------------------
// GEMM: C[M,N] = A[M,K]*B[N,K]^T with A,B as bf16 hi/lo pairs (K-major rows).
// 3-pass: Ahi*Bhi + Ahi*Blo + Alo*Bhi, fp32 accumulate.
// CTA tile 128x128, BK=32, 8 warps (warp tile 64x32), 3-stage cp.async pipe,
// ONE __syncthreads per mainloop iteration (loads issued right after sync).
// SMEM tile row layout: 128 bytes = [hi 32 bf16 | lo 32 bf16], SW128 swizzle.
// EPI: 0=fp32 C; 1=hi/lo bf16 of acc*escale; 2=transpose hi/lo via SMEM stage
// ---------------------------------------------------------------------------
#define STAGES    3
#define TILE_HB   16384                  // one operand tile: 128 rows * 128B
#define STAGE_B   (2 * TILE_HB)          // A + B
#define GSMEM     (STAGES * STAGE_B)     // 96 KB

__device__ __forceinline__ void issue_stage_load(
    uint32_t tile_u,
    const __nv_bfloat16* __restrict__ Ahi, const __nv_bfloat16* __restrict__ Alo,
    const __nv_bfloat16* __restrict__ Bhi, const __nv_bfloat16* __restrict__ Blo,
    int m0, int n0, int K, int kc, int t)
{
    const int r  = t >> 1;               // 0..127
    const int h  = t & 1;                // 0 -> chunks 0..3 (hi), 1 -> 4..7 (lo)
#pragma unroll
    for (int c = 0; c < 4; c++) {
        int c8 = h * 4 + c;
        const __nv_bfloat16* src = (c8 < 4 ? Ahi : Alo);
        const __nv_bfloat16* s = src + (size_t)(m0 + r) * K + kc * 32 + (c8 & 3) * 8;
        CP_ASYNC16(tile_u + SWZ((uint32_t)(r * 128 + c8 * 16)), s);
    }
#pragma unroll
    for (int c = 0; c < 4; c++) {
        int c8 = h * 4 + c;
        const __nv_bfloat16* src = (c8 < 4 ? Bhi : Blo);
        const __nv_bfloat16* s = src + (size_t)(n0 + r) * K + kc * 32 + (c8 & 3) * 8;
        CP_ASYNC16(tile_u + TILE_HB + SWZ((uint32_t)(r * 128 + c8 * 16)), s);
    }
}

template <int EPI>
__global__ __launch_bounds__(256, 2) void gemm_mma3(
    const __nv_bfloat16* __restrict__ Ahi, const __nv_bfloat16* __restrict__ Alo,
    const __nv_bfloat16* __restrict__ Bhi, const __nv_bfloat16* __restrict__ Blo,
    float* __restrict__ Cf, __nv_bfloat16* __restrict__ Chi,
    __nv_bfloat16* __restrict__ Clo,
    int M, int N, int K,
    size_t sA, size_t sB, size_t sC, float escale)
{
    extern __shared__ char smem[];
    const uint32_t sb = smem_u32(smem);
    const int t     = threadIdx.x;
    const int wid   = t >> 5;
    const int lane  = t & 31;
    const int warpm = wid >> 2;          // 0..1
    const int warpn = wid & 3;           // 0..3
    const int m0    = blockIdx.y * 128;
    const int n0    = blockIdx.x * 128;
    const size_t zb = blockIdx.z;

    Ahi += zb * sA;  Alo += zb * sA;
    Bhi += zb * sB;  Blo += zb * sB;

    float acc[4][4][4];
#pragma unroll
    for (int i = 0; i < 4; i++)
#pragma unroll
        for (int j = 0; j < 4; j++)
#pragma unroll
            for (int c = 0; c < 4; c++) acc[i][j][c] = 0.0f;

    const int nch = K / 32;

    // prologue: prefetch 2 stages
    issue_stage_load(sb + 0 * STAGE_B, Ahi, Alo, Bhi, Blo, m0, n0, K, 0, t);
    CP_COMMIT();
    issue_stage_load(sb + 1 * STAGE_B, Ahi, Alo, Bhi, Blo, m0, n0, K, 1, t);
    CP_COMMIT();

    // per-lane invariant address pieces
    const uint32_t a_row  = (uint32_t)(warpm * 64 + (lane & 15));   // + mt*16
    const uint32_t a_k16b = ((lane >> 4) & 1) * 16;
    const uint32_t b_row  = (uint32_t)(warpn * 32 + (lane & 7));    // + nt*8
    const uint32_t b_k16b = ((lane >> 3) & 1) * 16;

    for (int kc = 0; kc < nch; kc++) {
        CP_WAIT1();
        __syncthreads();          // all warps done reading stage (kc-1)%3

        // issue next loads FIRST so cp.async overlaps the whole compute body;
        // target slot (kc+2)%3 == (kc-1)%3, safe after the sync above.
        if (kc + 2 < nch) {
            issue_stage_load(sb + ((kc + 2) % STAGES) * STAGE_B,
                             Ahi, Alo, Bhi, Blo, m0, n0, K, kc + 2, t);
        }
        CP_COMMIT();              // keep group count in lockstep on tail too

        const uint32_t tu = sb + (kc % STAGES) * STAGE_B;

#pragma unroll
        for (int k16 = 0; k16 < 2; k16++) {
            uint32_t a[4][4], bh[4][2], bl[4][2];
#pragma unroll
            for (int mt = 0; mt < 4; mt++) {
                uint32_t bo = (a_row + mt * 16) * 128 + 0 + k16 * 32 + a_k16b;
                LDSM_X4(a[mt][0], a[mt][1], a[mt][2], a[mt][3], tu + SWZ(bo));
            }
#pragma unroll
            for (int nt = 0; nt < 4; nt++) {
                uint32_t boh = (b_row + nt * 8) * 128 + 0  + k16 * 32 + b_k16b;
                uint32_t bol = (b_row + nt * 8) * 128 + 64 + k16 * 32 + b_k16b;
                LDSM_X2(bh[nt][0], bh[nt][1], tu + TILE_HB + SWZ(boh));
                LDSM_X2(bl[nt][0], bl[nt][1], tu + TILE_HB + SWZ(bol));
            }
            // HH + HL
#pragma unroll
            for (int mt = 0; mt < 4; mt++)
#pragma unroll
                for (int nt = 0; nt < 4; nt++) MMA16816(acc[mt][nt], a[mt], bh[nt]);
#pragma unroll
            for (int mt = 0; mt < 4; mt++)
#pragma unroll
                for (int nt = 0; nt < 4; nt++) MMA16816(acc[mt][nt], a[mt], bl[nt]);
            // A lo (reuse regs) + LH
#pragma unroll
            for (int mt = 0; mt < 4; mt++) {
                uint32_t bo = (a_row + mt * 16) * 128 + 64 + k16 * 32 + a_k16b;
                LDSM_X4(a[mt][0], a[mt][1], a[mt][2], a[mt][3], tu + SWZ(bo));
            }
#pragma unroll
            for (int mt = 0; mt < 4; mt++)
#pragma unroll
                for (int nt = 0; nt < 4; nt++) MMA16816(acc[mt][nt], a[mt], bh[nt]);
        }
    }
    CP_WAIT0();

    const int rbase = lane >> 2;           // 0..7
    const int cbase = (lane & 3) * 2;

    if (EPI == 2) {
        // ---- stage transposed tile in SMEM, then coalesced writeout ----
        __syncthreads();                   // done with pipeline buffers
        float* stg = (float*)smem;         // [128 cols][129] fp32 = 66 KB
#pragma unroll
        for (int mt = 0; mt < 4; mt++) {
#pragma unroll
            for (int nt = 0; nt < 4; nt++) {
                int row = warpm * 64 + mt * 16 + rbase;   // s_local
                int col = warpn * 32 + nt * 8 + cbase;    // n_local
                float* d = acc[mt][nt];
                stg[(col + 0) * 129 + row + 0] = d[0];
                stg[(col + 1) * 129 + row + 0] = d[1];
                stg[(col + 0) * 129 + row + 8] = d[2];
                stg[(col + 1) * 129 + row + 8] = d[3];
            }
        }
        __syncthreads();
        const int n_l = t >> 1;            // 0..127
        const int hf  = t & 1;             // s half: 0..63 / 64..127
        const int b   = m0 >> 11;
        const int s0  = (m0 & 2047) + hf * 64;
        const size_t obase = ((size_t)(b * DIM + n0 + n_l)) * SEQ + s0;
#pragma unroll
        for (int j8 = 0; j8 < 8; j8++) {   // 8 groups of 8 elems
            ushort hp[8], lp[8];
#pragma unroll
            for (int e = 0; e < 8; e++) {
                float v = stg[n_l * 129 + hf * 64 + j8 * 8 + e] * escale;
                __nv_bfloat16 h = __float2bfloat16(v);
                __nv_bfloat16 l = __float2bfloat16(v - __bfloat162float(h));
                hp[e] = __bfloat16_as_ushort(h);
                lp[e] = __bfloat16_as_ushort(l);
            }
            *(uint4*)&Chi[obase + j8 * 8] = *(uint4*)hp;
            *(uint4*)&Clo[obase + j8 * 8] = *(uint4*)lp;
        }
        return;
    }

    // ---- direct register epilogues (coalesced) ----
#pragma unroll
    for (int mt = 0; mt < 4; mt++) {
#pragma unroll
        for (int nt = 0; nt < 4; nt++) {
            int row = m0 + warpm * 64 + mt * 16 + rbase;
            int col = n0 + warpn * 32 + nt * 8 + cbase;
            float* d = acc[mt][nt];
            if (EPI == 0) {
                float* Cb = Cf + zb * sC;
                *(float2*)&Cb[(size_t)row * N + col]       = make_float2(d[0], d[1]);
                *(float2*)&Cb[(size_t)(row + 8) * N + col] = make_float2(d[2], d[3]);
            } else {   // EPI == 1
#pragma unroll
                for (int hrow = 0; hrow < 2; hrow++) {
                    float a0 = d[hrow * 2 + 0] * escale;
                    float a1 = d[hrow * 2 + 1] * escale;
                    __nv_bfloat16 h0 = __float2bfloat16(a0);
                    __nv_bfloat16 h1 = __float2bfloat16(a1);
                    __nv_bfloat16 l0 = __float2bfloat16(a0 - __bfloat162float(h0));
                    __nv_bfloat16 l1 = __float2bfloat16(a1 - __bfloat162float(h1));
                    size_t idx = (size_t)(row + hrow * 8) * N + col;
                    *(uint32_t*)&Chi[idx] = (uint32_t)__bfloat16_as_ushort(h0) |
                                            ((uint32_t)__bfloat16_as_ushort(h1) << 16);
                    *(uint32_t*)&Clo[idx] = (uint32_t)__bfloat16_as_ushort(l0) |
                                            ((uint32_t)__bfloat16_as_ushort(l1) << 16);
                }
            }
        }
    }
}

// ---------------------------------------------------------------------------
// fp32 -> bf16 hi/lo split (vectorized by 4)
// ---------------------------------------------------------------------------
__global__ __launch_bounds__(256) void split_kernel(
    const float* __restrict__ src, __nv_bfloat16* __restrict__ hi,
    __nv_bfloat16* __restrict__ lo, int n4)
{
    int i = blockIdx.x * blockDim.x + threadIdx.x;
    if (i >= n4) return;
    float4 x = ((const float4*)src)[i];
    float a[4] = {x.x, x.y, x.z, x.w};
    uint32_t hp[2], lp[2];
#pragma unroll
    for (int j = 0; j < 2; j++) {
        __nv_bfloat16 h0 = __float2bfloat16(a[j * 2 + 0]);
        __nv_bfloat16 h1 = __float2bfloat16(a[j * 2 + 1]);
        __nv_bfloat16 l0 = __float2bfloat16(a[j * 2 + 0] - __bfloat162float(h0));
        __nv_bfloat16 l1 = __float2bfloat16(a[j * 2 + 1] - __bfloat162float(h1));
        hp[j] = (uint32_t)__bfloat16_as_ushort(h0) | ((uint32_t)__bfloat16_as_ushort(h1) << 16);
        lp[j] = (uint32_t)__bfloat16_as_ushort(l0) | ((uint32_t)__bfloat16_as_ushort(l1) << 16);
    }
    ((uint2*)hi)[i] = make_uint2(hp[0], hp[1]);
    ((uint2*)lo)[i] = make_uint2(lp[0], lp[1]);
}

// ---------------------------------------------------------------------------
// Softmax over rows of S (pre-scaled via Q), writes P hi/lo bf16.
// One block (256 threads) per row of 2048.
// ---------------------------------------------------------------------------
__global__ __launch_bounds__(256) void softmax_split_kernel(
    const float* __restrict__ S, __nv_bfloat16* __restrict__ Phi,
    __nv_bfloat16* __restrict__ Plo)
{
    const float* row = S + (size_t)blockIdx.x * SEQ;
    __nv_bfloat16* ph = Phi + (size_t)blockIdx.x * SEQ;
    __nv_bfloat16* pl = Plo + (size_t)blockIdx.x * SEQ;
    const int t = threadIdx.x;
    __shared__ float red[256];

    float v[8];
#pragma unroll
    for (int i = 0; i < 8; i++) v[i] = row[t + i * 256];

    float lmax = v[0];
#pragma unroll
    for (int i = 1; i < 8; i++) lmax = fmaxf(lmax, v[i]);
    red[t] = lmax;
    __syncthreads();
    for (int s = 128; s > 0; s >>= 1) {
        if (t < s) red[t] = fmaxf(red[t], red[t + s]);
        __syncthreads();
    }
    const float m = red[0];
    __syncthreads();

    float lsum = 0.0f;
#pragma unroll
    for (int i = 0; i < 8; i++) { v[i] = __expf(v[i] - m); lsum += v[i]; }
    red[t] = lsum;
    __syncthreads();
    for (int s = 128; s > 0; s >>= 1) {
        if (t < s) red[t] += red[t + s];
        __syncthreads();
    }
    const float inv = 1.0f / red[0];

#pragma unroll
    for (int i = 0; i < 8; i++) {
        float p = v[i] * inv;
        __nv_bfloat16 h = __float2bfloat16(p);
        ph[t + i * 256] = h;
        pl[t + i * 256] = __float2bfloat16(p - __bfloat162float(h));
    }
}

// ---------------------------------------------------------------------------
// kernel_launch : x, W_key, W_query, W_value -> context (fp32)
// ---------------------------------------------------------------------------
extern "C" void kernel_launch(void* const* d_in, const int* in_sizes, int n_in,
                              void* d_out, int out_size)
{
    const float* x  = (const float*)d_in[0];
    const float* Wk = (const float*)d_in[1];
    const float* Wq = (const float*)d_in[2];
    const float* Wv = (const float*)d_in[3];
    float* out = (float*)d_out;

    float* S;
    __nv_bfloat16 *Xhi, *Xlo, *Wqhi, *Wqlo, *Wkhi, *Wklo, *Wvhi, *Wvlo;
    __nv_bfloat16 *Qhi, *Qlo, *Khi, *Klo, *Vthi, *Vtlo, *Phi, *Plo;
    cudaGetSymbolAddress((void**)&S,    g_S);
    cudaGetSymbolAddress((void**)&Xhi,  g_Xhi);  cudaGetSymbolAddress((void**)&Xlo,  g_Xlo);
    cudaGetSymbolAddress((void**)&Wqhi, g_Wqhi); cudaGetSymbolAddress((void**)&Wqlo, g_Wqlo);
    cudaGetSymbolAddress((void**)&Wkhi, g_Wkhi); cudaGetSymbolAddress((void**)&Wklo, g_Wklo);
    cudaGetSymbolAddress((void**)&Wvhi, g_Wvhi); cudaGetSymbolAddress((void**)&Wvlo, g_Wvlo);
    cudaGetSymbolAddress((void**)&Qhi,  g_Qhi);  cudaGetSymbolAddress((void**)&Qlo,  g_Qlo);
    cudaGetSymbolAddress((void**)&Khi,  g_Khi);  cudaGetSymbolAddress((void**)&Klo,  g_Klo);
    cudaGetSymbolAddress((void**)&Vthi, g_Vthi); cudaGetSymbolAddress((void**)&Vtlo, g_Vtlo);
    cudaGetSymbolAddress((void**)&Phi,  g_Phi);  cudaGetSymbolAddress((void**)&Plo,  g_Plo);

    cudaFuncSetAttribute(gemm_mma3<0>, cudaFuncAttributeMaxDynamicSharedMemorySize, GSMEM);
    cudaFuncSetAttribute(gemm_mma3<1>, cudaFuncAttributeMaxDynamicSharedMemorySize, GSMEM);
    cudaFuncSetAttribute(gemm_mma3<2>, cudaFuncAttributeMaxDynamicSharedMemorySize, GSMEM);

    // 1) split inputs into bf16 hi/lo
    split_kernel<<<(MQ * DIM / 4 + 255) / 256, 256>>>(x,  Xhi,  Xlo,  MQ * DIM / 4);
    split_kernel<<<(DIM * DIM / 4 + 255) / 256, 256>>>(Wq, Wqhi, Wqlo, DIM * DIM / 4);
    split_kernel<<<(DIM * DIM / 4 + 255) / 256, 256>>>(Wk, Wkhi, Wklo, DIM * DIM / 4);
    split_kernel<<<(DIM * DIM / 4 + 255) / 256, 256>>>(Wv, Wvhi, Wvlo, DIM * DIM / 4);

    // 2) projections: Q (scaled by 1/32, split), K (split), V (transpose-split)
    {
        dim3 grid(DIM / 128, MQ / 128, 1);
        gemm_mma3<1><<<grid, 256, GSMEM>>>(Xhi, Xlo, Wqhi, Wqlo,
            nullptr, Qhi, Qlo, MQ, DIM, DIM, 0, 0, 0, 1.0f / 32.0f);
        gemm_mma3<1><<<grid, 256, GSMEM>>>(Xhi, Xlo, Wkhi, Wklo,
            nullptr, Khi, Klo, MQ, DIM, DIM, 0, 0, 0, 1.0f);
        gemm_mma3<2><<<grid, 256, GSMEM>>>(Xhi, Xlo, Wvhi, Wvlo,
            nullptr, Vthi, Vtlo, MQ, DIM, DIM, 0, 0, 0, 1.0f);
    }

    // 3) scores[b] = Qs[b] * K[b]^T  (already scaled) -> fp32 S
    {
        dim3 grid(SEQ / 128, SEQ / 128, BATCH);
        gemm_mma3<0><<<grid, 256, GSMEM>>>(Qhi, Qlo, Khi, Klo,
            S, nullptr, nullptr, SEQ, SEQ, DIM,
            (size_t)SEQ * DIM, (size_t)SEQ * DIM, (size_t)SEQ * SEQ, 1.0f);
    }

    // 4) softmax rows -> P hi/lo bf16
    softmax_split_kernel<<<BATCH * SEQ, 256>>>(S, Phi, Plo);

    // 5) context[b] = P[b] * Vt[b]^T -> out fp32
    {
        dim3 grid(DIM / 128, SEQ / 128, BATCH);
        gemm_mma3<0><<<grid, 256, GSMEM>>>(Phi, Plo, Vthi, Vtlo,
            out, nullptr, nullptr, SEQ, DIM, SEQ,
            (size_t)SEQ * SEQ, (size_t)DIM * SEQ, (size_t)SEQ * DIM, 1.0f);
    }
}

// round 9
// speedup vs baseline: 1.6062x; 1.6062x over previous
#include <cuda_runtime.h>
#include <cuda_fp16.h>
#include <math.h>
#include <stdint.h>

#define BATCH 4
#define SEQ   2048
#define DIM   1024
#define MQ    (BATCH * SEQ)      // 8192

// ---------------------------------------------------------------------------
// Device scratch (no allocation allowed).  All splits are fp16 hi/lo.
// ---------------------------------------------------------------------------
__device__ float  g_S[BATCH * SEQ * SEQ];            // fp32 scores
__device__ __half g_Xhi[MQ * DIM],  g_Xlo[MQ * DIM];
__device__ __half g_Wqhi[DIM * DIM], g_Wqlo[DIM * DIM];
__device__ __half g_Wkhi[DIM * DIM], g_Wklo[DIM * DIM];
__device__ __half g_Wvhi[DIM * DIM], g_Wvlo[DIM * DIM];
__device__ __half g_Qhi[MQ * DIM],  g_Qlo[MQ * DIM];
__device__ __half g_Khi[MQ * DIM],  g_Klo[MQ * DIM];
__device__ __half g_Vthi[MQ * DIM], g_Vtlo[MQ * DIM];   // [B][D][S]
__device__ __half g_Phi[BATCH * SEQ * SEQ], g_Plo[BATCH * SEQ * SEQ];

// ---------------------------------------------------------------------------
// PTX helpers (sm_80-class ISA: cp.async, ldmatrix, mma.sync)
// ---------------------------------------------------------------------------
__device__ __forceinline__ uint32_t smem_u32(const void* p) {
    uint32_t a;
    asm("{ .reg .u64 t; cvta.to.shared.u64 t, %1; cvt.u32.u64 %0, t; }"
        : "=r"(a) : "l"(p));
    return a;
}

#define CP_ASYNC16(dst, src) \
    asm volatile("cp.async.cg.shared.global [%0], [%1], 16;" :: "r"(dst), "l"(src))
#define CP_COMMIT() asm volatile("cp.async.commit_group;" ::: "memory")
#define CP_WAIT1()  asm volatile("cp.async.wait_group 1;"  ::: "memory")
#define CP_WAIT0()  asm volatile("cp.async.wait_group 0;"  ::: "memory")

#define LDSM_X4(r0, r1, r2, r3, addr) \
    asm volatile("ldmatrix.sync.aligned.m8n8.x4.shared.b16 {%0,%1,%2,%3}, [%4];" \
                 : "=r"(r0), "=r"(r1), "=r"(r2), "=r"(r3) : "r"(addr))
#define LDSM_X2(r0, r1, addr) \
    asm volatile("ldmatrix.sync.aligned.m8n8.x2.shared.b16 {%0,%1}, [%2];" \
                 : "=r"(r0), "=r"(r1) : "r"(addr))

// fp16 inputs, fp32 accumulate
#define MMA16816(d, a, b) \
    asm volatile("mma.sync.aligned.m16n8k16.row.col.f32.f16.f16.f32 " \
                 "{%0,%1,%2,%3},{%4,%5,%6,%7},{%8,%9},{%0,%1,%2,%3};" \
                 : "+f"((d)[0]), "+f"((d)[1]), "+f"((d)[2]), "+f"((d)[3]) \
                 : "r"((a)[0]), "r"((a)[1]), "r"((a)[2]), "r"((a)[3]), \
                   "r"((b)[0]), "r"((b)[1]))

#define SWZ(bo) ((bo) ^ (((bo) >> 3) & 0x70))

__device__ __forceinline__ void split_hl(float v, __half& h, __half& l) {
    h = __float2half_rn(v);
    l = __float2half_rn(v - __half2float(h));
}

// ---------------------------------------------------------------------------
// GEMM: C[M,N] = A[M,K]*B[N,K]^T.  A as fp16 hi/lo (exact), B hi-only.
// 2-pass: Ahi*Bhi + Alo*Bhi  (= A_exact * Bhi; error ~2^-11 from B trunc).
// CTA tile 128x128, BK=32, 8 warps (warp tile 64x32), 3-stage cp.async pipe.
// SMEM A row: 128B = [hi 32 fp16 | lo 32 fp16]; B row: first 64B = hi only.
// EPI: 0=fp32 C; 1=hi/lo fp16 of acc*escale; 2=transpose hi/lo via SMEM stage
// ---------------------------------------------------------------------------
#define STAGES    3
#define TILE_HB   16384                  // A tile region: 128 rows * 128B
#define STAGE_B   (2 * TILE_HB)          // A + B regions (B uses half of its)
#define GSMEM     (STAGES * STAGE_B)     // 96 KB

__device__ __forceinline__ void issue_stage_load(
    uint32_t tile_u,
    const __half* __restrict__ Ahi, const __half* __restrict__ Alo,
    const __half* __restrict__ Bhi,
    int m0, int n0, int K, int kc, int t)
{
    const int r  = t >> 1;               // 0..127
    const int h  = t & 1;
    // A tile: hi (chunks 0..3) + lo (chunks 4..7)
#pragma unroll
    for (int c = 0; c < 4; c++) {
        int c8 = h * 4 + c;
        const __half* src = (c8 < 4 ? Ahi : Alo);
        const __half* s = src + (size_t)(m0 + r) * K + kc * 32 + (c8 & 3) * 8;
        CP_ASYNC16(tile_u + SWZ((uint32_t)(r * 128 + c8 * 16)), s);
    }
    // B tile: hi only (first 64B of each row), 2 chunks per thread
#pragma unroll
    for (int c = 0; c < 2; c++) {
        int c4 = h * 2 + c;              // 0..3
        const __half* s = Bhi + (size_t)(n0 + r) * K + kc * 32 + c4 * 8;
        CP_ASYNC16(tile_u + TILE_HB + SWZ((uint32_t)(r * 128 + c4 * 16)), s);
    }
}

template <int EPI>
__global__ __launch_bounds__(256, 2) void gemm_mma2(
    const __half* __restrict__ Ahi, const __half* __restrict__ Alo,
    const __half* __restrict__ Bhi,
    float* __restrict__ Cf, __half* __restrict__ Chi, __half* __restrict__ Clo,
    int M, int N, int K,
    size_t sA, size_t sB, size_t sC, float escale)
{
    extern __shared__ char smem[];
    const uint32_t sb = smem_u32(smem);
    const int t     = threadIdx.x;
    const int wid   = t >> 5;
    const int lane  = t & 31;
    const int warpm = wid >> 2;          // 0..1
    const int warpn = wid & 3;           // 0..3
    const int m0    = blockIdx.y * 128;
    const int n0    = blockIdx.x * 128;
    const size_t zb = blockIdx.z;

    Ahi += zb * sA;  Alo += zb * sA;  Bhi += zb * sB;

    float acc[4][4][4];
#pragma unroll
    for (int i = 0; i < 4; i++)
#pragma unroll
        for (int j = 0; j < 4; j++)
#pragma unroll
            for (int c = 0; c < 4; c++) acc[i][j][c] = 0.0f;

    const int nch = K / 32;

    issue_stage_load(sb + 0 * STAGE_B, Ahi, Alo, Bhi, m0, n0, K, 0, t);
    CP_COMMIT();
    issue_stage_load(sb + 1 * STAGE_B, Ahi, Alo, Bhi, m0, n0, K, 1, t);
    CP_COMMIT();

    const uint32_t a_row  = (uint32_t)(warpm * 64 + (lane & 15));   // + mt*16
    const uint32_t a_k16b = ((lane >> 4) & 1) * 16;
    const uint32_t b_row  = (uint32_t)(warpn * 32 + (lane & 7));    // + nt*8
    const uint32_t b_k16b = ((lane >> 3) & 1) * 16;

    for (int kc = 0; kc < nch; kc++) {
        CP_WAIT1();
        __syncthreads();

        if (kc + 2 < nch) {
            issue_stage_load(sb + ((kc + 2) % STAGES) * STAGE_B,
                             Ahi, Alo, Bhi, m0, n0, K, kc + 2, t);
        }
        CP_COMMIT();

        const uint32_t tu = sb + (kc % STAGES) * STAGE_B;

#pragma unroll
        for (int k16 = 0; k16 < 2; k16++) {
            uint32_t a[4][4], bh[4][2];
            // A hi fragments
#pragma unroll
            for (int mt = 0; mt < 4; mt++) {
                uint32_t bo = (a_row + mt * 16) * 128 + 0 + k16 * 32 + a_k16b;
                LDSM_X4(a[mt][0], a[mt][1], a[mt][2], a[mt][3], tu + SWZ(bo));
            }
            // B hi fragments
#pragma unroll
            for (int nt = 0; nt < 4; nt++) {
                uint32_t boh = (b_row + nt * 8) * 128 + k16 * 32 + b_k16b;
                LDSM_X2(bh[nt][0], bh[nt][1], tu + TILE_HB + SWZ(boh));
            }
            // HH
#pragma unroll
            for (int mt = 0; mt < 4; mt++)
#pragma unroll
                for (int nt = 0; nt < 4; nt++) MMA16816(acc[mt][nt], a[mt], bh[nt]);
            // A lo (reuse regs) + LH
#pragma unroll
            for (int mt = 0; mt < 4; mt++) {
                uint32_t bo = (a_row + mt * 16) * 128 + 64 + k16 * 32 + a_k16b;
                LDSM_X4(a[mt][0], a[mt][1], a[mt][2], a[mt][3], tu + SWZ(bo));
            }
#pragma unroll
            for (int mt = 0; mt < 4; mt++)
#pragma unroll
                for (int nt = 0; nt < 4; nt++) MMA16816(acc[mt][nt], a[mt], bh[nt]);
        }
    }
    CP_WAIT0();

    const int rbase = lane >> 2;           // 0..7
    const int cbase = (lane & 3) * 2;

    if (EPI == 2) {
        // ---- stage transposed tile in SMEM, then coalesced writeout ----
        __syncthreads();
        float* stg = (float*)smem;         // [128 cols][129] fp32 = 66 KB
#pragma unroll
        for (int mt = 0; mt < 4; mt++) {
#pragma unroll
            for (int nt = 0; nt < 4; nt++) {
                int row = warpm * 64 + mt * 16 + rbase;   // s_local
                int col = warpn * 32 + nt * 8 + cbase;    // n_local
                float* d = acc[mt][nt];
                stg[(col + 0) * 129 + row + 0] = d[0];
                stg[(col + 1) * 129 + row + 0] = d[1];
                stg[(col + 0) * 129 + row + 8] = d[2];
                stg[(col + 1) * 129 + row + 8] = d[3];
            }
        }
        __syncthreads();
        const int n_l = t >> 1;            // 0..127
        const int hf  = t & 1;
        const int b   = m0 >> 11;
        const int s0  = (m0 & 2047) + hf * 64;
        const size_t obase = ((size_t)(b * DIM + n0 + n_l)) * SEQ + s0;
#pragma unroll
        for (int j8 = 0; j8 < 8; j8++) {
            ushort hp[8], lp[8];
#pragma unroll
            for (int e = 0; e < 8; e++) {
                float v = stg[n_l * 129 + hf * 64 + j8 * 8 + e] * escale;
                __half h, l;  split_hl(v, h, l);
                hp[e] = __half_as_ushort(h);
                lp[e] = __half_as_ushort(l);
            }
            *(uint4*)&Chi[obase + j8 * 8] = *(uint4*)hp;
            *(uint4*)&Clo[obase + j8 * 8] = *(uint4*)lp;
        }
        return;
    }

#pragma unroll
    for (int mt = 0; mt < 4; mt++) {
#pragma unroll
        for (int nt = 0; nt < 4; nt++) {
            int row = m0 + warpm * 64 + mt * 16 + rbase;
            int col = n0 + warpn * 32 + nt * 8 + cbase;
            float* d = acc[mt][nt];
            if (EPI == 0) {
                float* Cb = Cf + zb * sC;
                *(float2*)&Cb[(size_t)row * N + col]       = make_float2(d[0], d[1]);
                *(float2*)&Cb[(size_t)(row + 8) * N + col] = make_float2(d[2], d[3]);
            } else {   // EPI == 1
#pragma unroll
                for (int hrow = 0; hrow < 2; hrow++) {
                    float a0 = d[hrow * 2 + 0] * escale;
                    float a1 = d[hrow * 2 + 1] * escale;
                    __half h0, l0, h1, l1;
                    split_hl(a0, h0, l0);
                    split_hl(a1, h1, l1);
                    size_t idx = (size_t)(row + hrow * 8) * N + col;
                    *(uint32_t*)&Chi[idx] = (uint32_t)__half_as_ushort(h0) |
                                            ((uint32_t)__half_as_ushort(h1) << 16);
                    *(uint32_t*)&Clo[idx] = (uint32_t)__half_as_ushort(l0) |
                                            ((uint32_t)__half_as_ushort(l1) << 16);
                }
            }
        }
    }
}

// ---------------------------------------------------------------------------
// fp32 -> fp16 hi/lo split (vectorized by 4)
// ---------------------------------------------------------------------------
__global__ __launch_bounds__(256) void split_kernel(
    const float* __restrict__ src, __half* __restrict__ hi,
    __half* __restrict__ lo, int n4)
{
    int i = blockIdx.x * blockDim.x + threadIdx.x;
    if (i >= n4) return;
    float4 x = ((const float4*)src)[i];
    float a[4] = {x.x, x.y, x.z, x.w};
    ushort hp[4], lp[4];
#pragma unroll
    for (int j = 0; j < 4; j++) {
        __half h, l;  split_hl(a[j], h, l);
        hp[j] = __half_as_ushort(h);
        lp[j] = __half_as_ushort(l);
    }
    ((uint2*)hi)[i] = *(uint2*)hp;
    ((uint2*)lo)[i] = *(uint2*)lp;
}

// ---------------------------------------------------------------------------
// Softmax over rows of S (pre-scaled via Q), writes P hi/lo fp16.
// One block (256 threads) per row of 2048.
// ---------------------------------------------------------------------------
__global__ __launch_bounds__(256) void softmax_split_kernel(
    const float* __restrict__ S, __half* __restrict__ Phi,
    __half* __restrict__ Plo)
{
    const float* row = S + (size_t)blockIdx.x * SEQ;
    __half* ph = Phi + (size_t)blockIdx.x * SEQ;
    __half* pl = Plo + (size_t)blockIdx.x * SEQ;
    const int t = threadIdx.x;
    __shared__ float red[256];

    float v[8];
#pragma unroll
    for (int i = 0; i < 8; i++) v[i] = row[t + i * 256];

    float lmax = v[0];
#pragma unroll
    for (int i = 1; i < 8; i++) lmax = fmaxf(lmax, v[i]);
    red[t] = lmax;
    __syncthreads();
    for (int s = 128; s > 0; s >>= 1) {
        if (t < s) red[t] = fmaxf(red[t], red[t + s]);
        __syncthreads();
    }
    const float m = red[0];
    __syncthreads();

    float lsum = 0.0f;
#pragma unroll
    for (int i = 0; i < 8; i++) { v[i] = __expf(v[i] - m); lsum += v[i]; }
    red[t] = lsum;
    __syncthreads();
    for (int s = 128; s > 0; s >>= 1) {
        if (t < s) red[t] += red[t + s];
        __syncthreads();
    }
    const float inv = 1.0f / red[0];

#pragma unroll
    for (int i = 0; i < 8; i++) {
        float p = v[i] * inv;
        __half h, l;  split_hl(p, h, l);
        ph[t + i * 256] = h;
        pl[t + i * 256] = l;
    }
}

// ---------------------------------------------------------------------------
// kernel_launch : x, W_key, W_query, W_value -> context (fp32)
// ---------------------------------------------------------------------------
extern "C" void kernel_launch(void* const* d_in, const int* in_sizes, int n_in,
                              void* d_out, int out_size)
{
    const float* x  = (const float*)d_in[0];
    const float* Wk = (const float*)d_in[1];
    const float* Wq = (const float*)d_in[2];
    const float* Wv = (const float*)d_in[3];
    float* out = (float*)d_out;

    float* S;
    __half *Xhi, *Xlo, *Wqhi, *Wqlo, *Wkhi, *Wklo, *Wvhi, *Wvlo;
    __half *Qhi, *Qlo, *Khi, *Klo, *Vthi, *Vtlo, *Phi, *Plo;
    cudaGetSymbolAddress((void**)&S,    g_S);
    cudaGetSymbolAddress((void**)&Xhi,  g_Xhi);  cudaGetSymbolAddress((void**)&Xlo,  g_Xlo);
    cudaGetSymbolAddress((void**)&Wqhi, g_Wqhi); cudaGetSymbolAddress((void**)&Wqlo, g_Wqlo);
    cudaGetSymbolAddress((void**)&Wkhi, g_Wkhi); cudaGetSymbolAddress((void**)&Wklo, g_Wklo);
    cudaGetSymbolAddress((void**)&Wvhi, g_Wvhi); cudaGetSymbolAddress((void**)&Wvlo, g_Wvlo);
    cudaGetSymbolAddress((void**)&Qhi,  g_Qhi);  cudaGetSymbolAddress((void**)&Qlo,  g_Qlo);
    cudaGetSymbolAddress((void**)&Khi,  g_Khi);  cudaGetSymbolAddress((void**)&Klo,  g_Klo);
    cudaGetSymbolAddress((void**)&Vthi, g_Vthi); cudaGetSymbolAddress((void**)&Vtlo, g_Vtlo);
    cudaGetSymbolAddress((void**)&Phi,  g_Phi);  cudaGetSymbolAddress((void**)&Plo,  g_Plo);

    cudaFuncSetAttribute(gemm_mma2<0>, cudaFuncAttributeMaxDynamicSharedMemorySize, GSMEM);
    cudaFuncSetAttribute(gemm_mma2<1>, cudaFuncAttributeMaxDynamicSharedMemorySize, GSMEM);
    cudaFuncSetAttribute(gemm_mma2<2>, cudaFuncAttributeMaxDynamicSharedMemorySize, GSMEM);

    // 1) split inputs into fp16 hi/lo
    split_kernel<<<(MQ * DIM / 4 + 255) / 256, 256>>>(x,  Xhi,  Xlo,  MQ * DIM / 4);
    split_kernel<<<(DIM * DIM / 4 + 255) / 256, 256>>>(Wq, Wqhi, Wqlo, DIM * DIM / 4);
    split_kernel<<<(DIM * DIM / 4 + 255) / 256, 256>>>(Wk, Wkhi, Wklo, DIM * DIM / 4);
    split_kernel<<<(DIM * DIM / 4 + 255) / 256, 256>>>(Wv, Wvhi, Wvlo, DIM * DIM / 4);

    // 2) projections: Q (scaled by 1/32, split), K (split), V (transpose-split)
    //    2-pass: X exact (hi/lo), W hi only.
    {
        dim3 grid(DIM / 128, MQ / 128, 1);
        gemm_mma2<1><<<grid, 256, GSMEM>>>(Xhi, Xlo, Wqhi,
            nullptr, Qhi, Qlo, MQ, DIM, DIM, 0, 0, 0, 1.0f / 32.0f);
        gemm_mma2<1><<<grid, 256, GSMEM>>>(Xhi, Xlo, Wkhi,
            nullptr, Khi, Klo, MQ, DIM, DIM, 0, 0, 0, 1.0f);
        gemm_mma2<2><<<grid, 256, GSMEM>>>(Xhi, Xlo, Wvhi,
            nullptr, Vthi, Vtlo, MQ, DIM, DIM, 0, 0, 0, 1.0f);
    }

    // 3) scores[b] = Qs[b] * K[b]^T  (already scaled) -> fp32 S
    {
        dim3 grid(SEQ / 128, SEQ / 128, BATCH);
        gemm_mma2<0><<<grid, 256, GSMEM>>>(Qhi, Qlo, Khi,
            S, nullptr, nullptr, SEQ, SEQ, DIM,
            (size_t)SEQ * DIM, (size_t)SEQ * DIM, (size_t)SEQ * SEQ, 1.0f);
    }

    // 4) softmax rows -> P hi/lo fp16
    softmax_split_kernel<<<BATCH * SEQ, 256>>>(S, Phi, Plo);

    // 5) context[b] = P[b] * Vt[b]^T -> out fp32
    {
        dim3 grid(DIM / 128, SEQ / 128, BATCH);
        gemm_mma2<0><<<grid, 256, GSMEM>>>(Phi, Plo, Vthi,
            out, nullptr, nullptr, SEQ, DIM, SEQ,
            (size_t)SEQ * SEQ, (size_t)DIM * SEQ, (size_t)SEQ * DIM, 1.0f);
    }
}

// round 10
// speedup vs baseline: 3.1990x; 1.9917x over previous
#include <cuda_runtime.h>
#include <cuda_fp16.h>
#include <math.h>
#include <stdint.h>

#define BATCH 4
#define SEQ   2048
#define DIM   1024
#define MQ    (BATCH * SEQ)      // 8192

// ---------------------------------------------------------------------------
// Device scratch (no allocation allowed). Single fp16 operands everywhere.
// ---------------------------------------------------------------------------
__device__ float  g_S[BATCH * SEQ * SEQ];            // fp32 scores
__device__ __half g_X [MQ * DIM];
__device__ __half g_Wq[DIM * DIM], g_Wk[DIM * DIM], g_Wv[DIM * DIM];
__device__ __half g_Q [MQ * DIM],  g_K [MQ * DIM];
__device__ __half g_Vt[MQ * DIM];                    // [B][D][S]
__device__ __half g_P [BATCH * SEQ * SEQ];

// ---------------------------------------------------------------------------
// PTX helpers (sm_80-class ISA: cp.async, ldmatrix, mma.sync)
// ---------------------------------------------------------------------------
__device__ __forceinline__ uint32_t smem_u32(const void* p) {
    uint32_t a;
    asm("{ .reg .u64 t; cvta.to.shared.u64 t, %1; cvt.u32.u64 %0, t; }"
        : "=r"(a) : "l"(p));
    return a;
}

#define CP_ASYNC16(dst, src) \
    asm volatile("cp.async.cg.shared.global [%0], [%1], 16;" :: "r"(dst), "l"(src))
#define CP_COMMIT() asm volatile("cp.async.commit_group;" ::: "memory")
#define CP_WAIT1()  asm volatile("cp.async.wait_group 1;"  ::: "memory")
#define CP_WAIT0()  asm volatile("cp.async.wait_group 0;"  ::: "memory")

#define LDSM_X4(r0, r1, r2, r3, addr) \
    asm volatile("ldmatrix.sync.aligned.m8n8.x4.shared.b16 {%0,%1,%2,%3}, [%4];" \
                 : "=r"(r0), "=r"(r1), "=r"(r2), "=r"(r3) : "r"(addr))
#define LDSM_X2(r0, r1, addr) \
    asm volatile("ldmatrix.sync.aligned.m8n8.x2.shared.b16 {%0,%1}, [%2];" \
                 : "=r"(r0), "=r"(r1) : "r"(addr))

// fp16 inputs, fp32 accumulate
#define MMA16816(d, a, b) \
    asm volatile("mma.sync.aligned.m16n8k16.row.col.f32.f16.f16.f32 " \
                 "{%0,%1,%2,%3},{%4,%5,%6,%7},{%8,%9},{%0,%1,%2,%3};" \
                 : "+f"((d)[0]), "+f"((d)[1]), "+f"((d)[2]), "+f"((d)[3]) \
                 : "r"((a)[0]), "r"((a)[1]), "r"((a)[2]), "r"((a)[3]), \
                   "r"((b)[0]), "r"((b)[1]))

#define SWZ(bo) ((bo) ^ (((bo) >> 3) & 0x70))

// ---------------------------------------------------------------------------
// GEMM: C[M,N] = A[M,K]*B[N,K]^T, plain fp16 operands, fp32 accumulate.
// CTA tile 128x128, BK=64 (128B row = 64 fp16), 8 warps (64x32 warp tile),
// 3-stage cp.async pipeline, one __syncthreads per iteration.
// EPI: 0=fp32 C; 1=fp16 of acc*escale; 2=transpose fp16 via SMEM stage
// ---------------------------------------------------------------------------
#define STAGES    3
#define TILE_HB   16384                  // one operand tile: 128 rows * 128B
#define STAGE_B   (2 * TILE_HB)          // A + B
#define GSMEM     (STAGES * STAGE_B)     // 96 KB

__device__ __forceinline__ void issue_stage_load(
    uint32_t tile_u,
    const __half* __restrict__ A, const __half* __restrict__ B,
    int m0, int n0, int K, int kc, int t)
{
    const int r = t >> 1;                // 0..127
    const int h = t & 1;                 // chunk-half selector
#pragma unroll
    for (int c = 0; c < 4; c++) {
        int c8 = h * 4 + c;              // 0..7, 16B chunks covering 64 fp16
        const __half* s = A + (size_t)(m0 + r) * K + kc * 64 + c8 * 8;
        CP_ASYNC16(tile_u + SWZ((uint32_t)(r * 128 + c8 * 16)), s);
    }
#pragma unroll
    for (int c = 0; c < 4; c++) {
        int c8 = h * 4 + c;
        const __half* s = B + (size_t)(n0 + r) * K + kc * 64 + c8 * 8;
        CP_ASYNC16(tile_u + TILE_HB + SWZ((uint32_t)(r * 128 + c8 * 16)), s);
    }
}

template <int EPI>
__global__ __launch_bounds__(256, 2) void gemm_f16(
    const __half* __restrict__ A, const __half* __restrict__ B,
    float* __restrict__ Cf, __half* __restrict__ Ch,
    int M, int N, int K,
    size_t sA, size_t sB, size_t sC, float escale)
{
    extern __shared__ char smem[];
    const uint32_t sb = smem_u32(smem);
    const int t     = threadIdx.x;
    const int wid   = t >> 5;
    const int lane  = t & 31;
    const int warpm = wid >> 2;          // 0..1
    const int warpn = wid & 3;           // 0..3
    const int m0    = blockIdx.y * 128;
    const int n0    = blockIdx.x * 128;
    const size_t zb = blockIdx.z;

    A += zb * sA;  B += zb * sB;

    float acc[4][4][4];
#pragma unroll
    for (int i = 0; i < 4; i++)
#pragma unroll
        for (int j = 0; j < 4; j++)
#pragma unroll
            for (int c = 0; c < 4; c++) acc[i][j][c] = 0.0f;

    const int nch = K / 64;

    issue_stage_load(sb + 0 * STAGE_B, A, B, m0, n0, K, 0, t);
    CP_COMMIT();
    issue_stage_load(sb + 1 * STAGE_B, A, B, m0, n0, K, 1, t);
    CP_COMMIT();

    const uint32_t a_row  = (uint32_t)(warpm * 64 + (lane & 15));   // + mt*16
    const uint32_t a_k16b = ((lane >> 4) & 1) * 16;
    const uint32_t b_row  = (uint32_t)(warpn * 32 + (lane & 7));    // + nt*8
    const uint32_t b_k16b = ((lane >> 3) & 1) * 16;

    for (int kc = 0; kc < nch; kc++) {
        CP_WAIT1();
        __syncthreads();

        if (kc + 2 < nch) {
            issue_stage_load(sb + ((kc + 2) % STAGES) * STAGE_B,
                             A, B, m0, n0, K, kc + 2, t);
        }
        CP_COMMIT();

        const uint32_t tu = sb + (kc % STAGES) * STAGE_B;

#pragma unroll
        for (int k16 = 0; k16 < 4; k16++) {     // 4 x K16 per 64-wide chunk
            uint32_t a[4][4], bh[4][2];
#pragma unroll
            for (int mt = 0; mt < 4; mt++) {
                uint32_t bo = (a_row + mt * 16) * 128 + k16 * 32 + a_k16b;
                LDSM_X4(a[mt][0], a[mt][1], a[mt][2], a[mt][3], tu + SWZ(bo));
            }
#pragma unroll
            for (int nt = 0; nt < 4; nt++) {
                uint32_t bo = (b_row + nt * 8) * 128 + k16 * 32 + b_k16b;
                LDSM_X2(bh[nt][0], bh[nt][1], tu + TILE_HB + SWZ(bo));
            }
#pragma unroll
            for (int mt = 0; mt < 4; mt++)
#pragma unroll
                for (int nt = 0; nt < 4; nt++) MMA16816(acc[mt][nt], a[mt], bh[nt]);
        }
    }
    CP_WAIT0();

    const int rbase = lane >> 2;           // 0..7
    const int cbase = (lane & 3) * 2;

    if (EPI == 2) {
        // ---- stage transposed tile in SMEM, then coalesced writeout ----
        __syncthreads();
        float* stg = (float*)smem;         // [128 cols][129] fp32 = 66 KB
#pragma unroll
        for (int mt = 0; mt < 4; mt++) {
#pragma unroll
            for (int nt = 0; nt < 4; nt++) {
                int row = warpm * 64 + mt * 16 + rbase;   // s_local
                int col = warpn * 32 + nt * 8 + cbase;    // n_local
                float* d = acc[mt][nt];
                stg[(col + 0) * 129 + row + 0] = d[0];
                stg[(col + 1) * 129 + row + 0] = d[1];
                stg[(col + 0) * 129 + row + 8] = d[2];
                stg[(col + 1) * 129 + row + 8] = d[3];
            }
        }
        __syncthreads();
        const int n_l = t >> 1;            // 0..127
        const int hf  = t & 1;
        const int b   = m0 >> 11;
        const int s0  = (m0 & 2047) + hf * 64;
        const size_t obase = ((size_t)(b * DIM + n0 + n_l)) * SEQ + s0;
#pragma unroll
        for (int j8 = 0; j8 < 8; j8++) {
            ushort hp[8];
#pragma unroll
            for (int e = 0; e < 8; e++) {
                float v = stg[n_l * 129 + hf * 64 + j8 * 8 + e] * escale;
                hp[e] = __half_as_ushort(__float2half_rn(v));
            }
            *(uint4*)&Ch[obase + j8 * 8] = *(uint4*)hp;
        }
        return;
    }

#pragma unroll
    for (int mt = 0; mt < 4; mt++) {
#pragma unroll
        for (int nt = 0; nt < 4; nt++) {
            int row = m0 + warpm * 64 + mt * 16 + rbase;
            int col = n0 + warpn * 32 + nt * 8 + cbase;
            float* d = acc[mt][nt];
            if (EPI == 0) {
                float* Cb = Cf + zb * sC;
                *(float2*)&Cb[(size_t)row * N + col]       = make_float2(d[0], d[1]);
                *(float2*)&Cb[(size_t)(row + 8) * N + col] = make_float2(d[2], d[3]);
            } else {   // EPI == 1 : fp16 store
#pragma unroll
                for (int hrow = 0; hrow < 2; hrow++) {
                    __half h0 = __float2half_rn(d[hrow * 2 + 0] * escale);
                    __half h1 = __float2half_rn(d[hrow * 2 + 1] * escale);
                    size_t idx = (size_t)(row + hrow * 8) * N + col;
                    *(uint32_t*)&Ch[idx] = (uint32_t)__half_as_ushort(h0) |
                                           ((uint32_t)__half_as_ushort(h1) << 16);
                }
            }
        }
    }
}

// ---------------------------------------------------------------------------
// fp32 -> fp16 convert (vectorized by 4)
// ---------------------------------------------------------------------------
__global__ __launch_bounds__(256) void cvt_kernel(
    const float* __restrict__ src, __half* __restrict__ dst, int n4)
{
    int i = blockIdx.x * blockDim.x + threadIdx.x;
    if (i >= n4) return;
    float4 x = ((const float4*)src)[i];
    ushort hp[4] = { __half_as_ushort(__float2half_rn(x.x)),
                     __half_as_ushort(__float2half_rn(x.y)),
                     __half_as_ushort(__float2half_rn(x.z)),
                     __half_as_ushort(__float2half_rn(x.w)) };
    ((uint2*)dst)[i] = *(uint2*)hp;
}

// ---------------------------------------------------------------------------
// Softmax over rows of S (pre-scaled via Q), writes P fp16.
// One block (256 threads) per row of 2048.
// ---------------------------------------------------------------------------
__global__ __launch_bounds__(256) void softmax_kernel(
    const float* __restrict__ S, __half* __restrict__ P)
{
    const float* row = S + (size_t)blockIdx.x * SEQ;
    __half* pr = P + (size_t)blockIdx.x * SEQ;
    const int t = threadIdx.x;
    __shared__ float red[256];

    float v[8];
#pragma unroll
    for (int i = 0; i < 8; i++) v[i] = row[t + i * 256];

    float lmax = v[0];
#pragma unroll
    for (int i = 1; i < 8; i++) lmax = fmaxf(lmax, v[i]);
    red[t] = lmax;
    __syncthreads();
    for (int s = 128; s > 0; s >>= 1) {
        if (t < s) red[t] = fmaxf(red[t], red[t + s]);
        __syncthreads();
    }
    const float m = red[0];
    __syncthreads();

    float lsum = 0.0f;
#pragma unroll
    for (int i = 0; i < 8; i++) { v[i] = __expf(v[i] - m); lsum += v[i]; }
    red[t] = lsum;
    __syncthreads();
    for (int s = 128; s > 0; s >>= 1) {
        if (t < s) red[t] += red[t + s];
        __syncthreads();
    }
    const float inv = 1.0f / red[0];

#pragma unroll
    for (int i = 0; i < 8; i++)
        pr[t + i * 256] = __float2half_rn(v[i] * inv);
}

// ---------------------------------------------------------------------------
// kernel_launch : x, W_key, W_query, W_value -> context (fp32)
// ---------------------------------------------------------------------------
extern "C" void kernel_launch(void* const* d_in, const int* in_sizes, int n_in,
                              void* d_out, int out_size)
{
    const float* x  = (const float*)d_in[0];
    const float* Wk = (const float*)d_in[1];
    const float* Wq = (const float*)d_in[2];
    const float* Wv = (const float*)d_in[3];
    float* out = (float*)d_out;

    float* S;
    __half *X, *Wqh, *Wkh, *Wvh, *Q, *K, *Vt, *P;
    cudaGetSymbolAddress((void**)&S,   g_S);
    cudaGetSymbolAddress((void**)&X,   g_X);
    cudaGetSymbolAddress((void**)&Wqh, g_Wq);
    cudaGetSymbolAddress((void**)&Wkh, g_Wk);
    cudaGetSymbolAddress((void**)&Wvh, g_Wv);
    cudaGetSymbolAddress((void**)&Q,   g_Q);
    cudaGetSymbolAddress((void**)&K,   g_K);
    cudaGetSymbolAddress((void**)&Vt,  g_Vt);
    cudaGetSymbolAddress((void**)&P,   g_P);

    cudaFuncSetAttribute(gemm_f16<0>, cudaFuncAttributeMaxDynamicSharedMemorySize, GSMEM);
    cudaFuncSetAttribute(gemm_f16<1>, cudaFuncAttributeMaxDynamicSharedMemorySize, GSMEM);
    cudaFuncSetAttribute(gemm_f16<2>, cudaFuncAttributeMaxDynamicSharedMemorySize, GSMEM);

    // 1) convert inputs to fp16
    cvt_kernel<<<(MQ * DIM / 4 + 255) / 256, 256>>>(x,  X,   MQ * DIM / 4);
    cvt_kernel<<<(DIM * DIM / 4 + 255) / 256, 256>>>(Wq, Wqh, DIM * DIM / 4);
    cvt_kernel<<<(DIM * DIM / 4 + 255) / 256, 256>>>(Wk, Wkh, DIM * DIM / 4);
    cvt_kernel<<<(DIM * DIM / 4 + 255) / 256, 256>>>(Wv, Wvh, DIM * DIM / 4);

    // 2) projections: Q (scaled by 1/32), K, V (transpose-store)
    {
        dim3 grid(DIM / 128, MQ / 128, 1);
        gemm_f16<1><<<grid, 256, GSMEM>>>(X, Wqh, nullptr, Q,
            MQ, DIM, DIM, 0, 0, 0, 1.0f / 32.0f);
        gemm_f16<1><<<grid, 256, GSMEM>>>(X, Wkh, nullptr, K,
            MQ, DIM, DIM, 0, 0, 0, 1.0f);
        gemm_f16<2><<<grid, 256, GSMEM>>>(X, Wvh, nullptr, Vt,
            MQ, DIM, DIM, 0, 0, 0, 1.0f);
    }

    // 3) scores[b] = Qs[b] * K[b]^T  (already scaled) -> fp32 S
    {
        dim3 grid(SEQ / 128, SEQ / 128, BATCH);
        gemm_f16<0><<<grid, 256, GSMEM>>>(Q, K, S, nullptr,
            SEQ, SEQ, DIM,
            (size_t)SEQ * DIM, (size_t)SEQ * DIM, (size_t)SEQ * SEQ, 1.0f);
    }

    // 4) softmax rows -> P fp16
    softmax_kernel<<<BATCH * SEQ, 256>>>(S, P);

    // 5) context[b] = P[b] * Vt[b]^T -> out fp32
    {
        dim3 grid(DIM / 128, SEQ / 128, BATCH);
        gemm_f16<0><<<grid, 256, GSMEM>>>(P, Vt, out, nullptr,
            SEQ, DIM, SEQ,
            (size_t)SEQ * SEQ, (size_t)DIM * SEQ, (size_t)SEQ * DIM, 1.0f);
    }
}